// round 16
// baseline (speedup 1.0000x reference)
#include <cuda_runtime.h>
#include <cuda_fp16.h>
#include <cuda_bf16.h>
#include <cstdint>

// Problem constants (fixed by the dataset)
#define DD   256          // hidden dim
#define BF   128          // B*F bases width
#define HBA  96           // H*B*A comb width
#define NCAT 224          // BF + HBA
#define GG   64           // graphs
#define EPSV 1e-5f

#define MAXN 50176
#define MAXE 851968

#define NTILES (NCAT / 8)     // 28 n-tiles of 8 cols
#define KSTEPS (256 / 8)      // 32 k-steps of 8
#define WFRAG_ELEMS (NTILES * KSTEPS * 32 * 2)

// ---------------- device scratch (no allocations allowed) ----------------
__device__ __half g_bases16[MAXN * BF];   // fp16 bases: only consumer is the k_agg gather
__device__ float g_comb [MAXN * HBA];
__device__ float g_h    [(size_t)MAXN * DD];
__device__ float g_Wfrag[WFRAG_ELEMS];    // B in mma-fragment layout, tf32-rounded
__device__ int   g_cnt  [MAXN];
__device__ int   g_off  [MAXN + 1];
__device__ int   g_cur  [MAXN];
__device__ int2  g_edge [MAXE];           // packed {src, bits(dinv[src]*dinv[dst])}
__device__ float g_dinv [MAXN];
__device__ float g_S1   [GG * DD];
__device__ float g_S2   [GG * DD];
__device__ float g_mu   [GG * DD];
__device__ float g_istd [GG * DD];
__device__ int   g_gstart[GG + 1];
__device__ int   g_bsum [64];
__device__ unsigned int g_bar;            // monotonic ticket barrier (replay-safe)

// ---------------- helpers ----------------
__device__ __forceinline__ float to_tf32(float x) {
    float r;
    asm("cvt.rna.tf32.f32 %0, %1;" : "=f"(r) : "f"(x));
    return r;
}
__device__ __forceinline__ uint32_t tf32_bits(float x) {
    float r;
    asm("cvt.rna.tf32.f32 %0, %1;" : "=f"(r) : "f"(x));
    return __float_as_uint(r);
}
// m16n8k8 tf32 mma (baseline sm_80+ PTX -> HMMA on sm_103, tensor pipe)
__device__ __forceinline__ void mma8(float* c, const uint32_t* a, uint32_t b0, uint32_t b1) {
    asm volatile(
        "mma.sync.aligned.m16n8k8.row.col.f32.tf32.tf32.f32 "
        "{%0,%1,%2,%3}, {%4,%5,%6,%7}, {%8,%9}, {%0,%1,%2,%3};"
        : "+f"(c[0]), "+f"(c[1]), "+f"(c[2]), "+f"(c[3])
        : "r"(a[0]), "r"(a[1]), "r"(a[2]), "r"(a[3]), "r"(b0), "r"(b1));
}
// gather one lane's 4 channels (4 halves = 8B) from a bases row, to f32
__device__ __forceinline__ float4 gather4(int row, int lane) {
    const uint2* p = reinterpret_cast<const uint2*>(g_bases16 + (size_t)row * BF);
    uint2 raw = __ldg(p + lane);
    __half2 h0 = *reinterpret_cast<__half2*>(&raw.x);
    __half2 h1 = *reinterpret_cast<__half2*>(&raw.y);
    float2 f0 = __half22float2(h0);
    float2 f1 = __half22float2(h1);
    return make_float4(f0.x, f0.y, f1.x, f1.y);
}
// software grid barrier: monotonic ticket counter, safe across graph replays
// (never reset; target = ticket rounded up to a multiple of nb).
// Requires all nb blocks co-resident (nb <= 148, 1 block/SM min).
__device__ __forceinline__ void grid_sync(int nb) {
    __syncthreads();
    if (threadIdx.x == 0) {
        __threadfence();
        unsigned int ticket = atomicAdd(&g_bar, 1u) + 1u;
        unsigned int target = ((ticket + (unsigned)nb - 1u) / (unsigned)nb) * (unsigned)nb;
        while (*((volatile unsigned int*)&g_bar) < target) { }
        __threadfence();
    }
    __syncthreads();
}

// ---------------- K-SETUP: one persistent kernel for the whole CSR build ----------------
// P0 zero+Wfrag+gstart | P1 histogram | P2 local scan | P2b block prefix | P3 scatter
__global__ __launch_bounds__(1024) void k_setup(int n, int e, int nb,
                                                const float* __restrict__ Wb,
                                                const float* __restrict__ Wc,
                                                const int* __restrict__ src,
                                                const int* __restrict__ dst,
                                                const int* __restrict__ batchv) {
    __shared__ int warpsums[32];
    __shared__ int red[64];
    int t = threadIdx.x;
    int b = blockIdx.x;
    int gtid = b * 1024 + t;
    int nt = nb * 1024;
    int lane = t & 31, wrp = t >> 5;

    // ---- P0: zeros, W fragment table, graph starts ----
    if (gtid < n) g_cnt[gtid] = 0;
    if (gtid < GG * DD) { g_S1[gtid] = 0.f; g_S2[gtid] = 0.f; }
    for (int i = gtid; i < WFRAG_ELEMS; i += nt) {
        int r    = i & 1;
        int ln   = (i >> 1) & 31;
        int ks   = (i >> 6) & 31;
        int ntl  = i >> 11;
        int gid = ln >> 2, tig = ln & 3;
        int k = ks * 8 + tig + r * 4;
        int nn = ntl * 8 + gid;
        float v = (nn < BF) ? Wb[k * BF + nn] : Wc[k * HBA + (nn - BF)];
        g_Wfrag[i] = to_tf32(v);
    }
    if (gtid <= GG) {
        if (gtid == GG) g_gstart[GG] = n;
        else {
            int lo = 0, hi = n;
            while (lo < hi) {
                int mid = (lo + hi) >> 1;
                if (batchv[mid] < gtid) lo = mid + 1; else hi = mid;
            }
            g_gstart[gtid] = lo;
        }
    }
    if (gtid == 0) g_off[n] = e;
    grid_sync(nb);

    // ---- P1: in-degree histogram over dst ----
    for (int i = gtid; i < e; i += nt) atomicAdd(&g_cnt[dst[i]], 1);
    grid_sync(nb);

    // ---- P2: per-block exclusive scan of tile b ----
    int i = gtid;
    int v = (i < n) ? g_cnt[i] : 0;
    int x = v;
    #pragma unroll
    for (int o = 1; o < 32; o <<= 1) {
        int y = __shfl_up_sync(0xFFFFFFFFu, x, o);
        if (lane >= o) x += y;
    }
    if (lane == 31) warpsums[wrp] = x;
    __syncthreads();
    if (t < 32) {
        int s = warpsums[t];
        #pragma unroll
        for (int o = 1; o < 32; o <<= 1) {
            int y = __shfl_up_sync(0xFFFFFFFFu, s, o);
            if (t >= o) s += y;
        }
        warpsums[t] = s;
    }
    __syncthreads();
    int incl = x + ((wrp > 0) ? warpsums[wrp - 1] : 0);
    if (t == 1023) g_bsum[b] = incl;
    grid_sync(nb);

    // ---- P2b: block prefix (nb <= 64) + write offsets ----
    if (t < 64) red[t] = (t < b) ? g_bsum[t] : 0;
    __syncthreads();
    if (t < 32) {
        int s = red[t] + red[t + 32];
        #pragma unroll
        for (int o = 16; o > 0; o >>= 1) s += __shfl_down_sync(0xFFFFFFFFu, s, o);
        if (t == 0) red[0] = s;
    }
    __syncthreads();
    int boff = red[0];
    if (i < n) {
        int eoff = (incl - v) + boff;
        g_off[i] = eoff;
        g_cur[i] = eoff;
        g_dinv[i] = rsqrtf((float)(v + 1));   // +1 self loop
    }
    grid_sync(nb);

    // ---- P3: scatter packed edge records {src, symweight} ----
    for (int j = gtid; j < e; j += nt) {
        int d = dst[j];
        int s = src[j];
        int p = atomicAdd(&g_cur[d], 1);
        float w = g_dinv[s] * g_dinv[d];
        g_edge[p] = make_int2(s, __float_as_int(w));
    }
}

// ---------------- K5: tensor-core TF32 GEMM via mma.sync (fallback HMMA path) ----------------
#define TBM 128
#define TBN 112
__global__ __launch_bounds__(256) void k_gemm_mma(const float* __restrict__ X,
                                                  const float* __restrict__ bcomb, int M) {
    int tid = threadIdx.x;
    int wid = tid >> 5, lane = tid & 31;
    int warp_m = wid & 3;        // 0..3
    int warp_n = wid >> 2;       // 0..1
    int gid = lane >> 2, tig = lane & 3;

    int rowb = blockIdx.x * TBM + warp_m * 32;          // warp's M base
    int coln0 = blockIdx.y * TBN + warp_n * 56;         // warp's N base
    int ntg0 = coln0 >> 3;                              // global n-tile base (7 tiles)

    // clamped row pointers (invalid rows compute garbage, stores are guarded)
    const float* A0 = X + (size_t)min(rowb + gid,      M - 1) * 256;
    const float* A1 = X + (size_t)min(rowb + gid + 8,  M - 1) * 256;
    const float* A2 = X + (size_t)min(rowb + gid + 16, M - 1) * 256;
    const float* A3 = X + (size_t)min(rowb + gid + 24, M - 1) * 256;

    const float2* Bf = reinterpret_cast<const float2*>(g_Wfrag);

    float acc[2][7][4];
    #pragma unroll
    for (int mt = 0; mt < 2; mt++)
        #pragma unroll
        for (int nt = 0; nt < 7; nt++)
            #pragma unroll
            for (int q = 0; q < 4; q++) acc[mt][nt][q] = 0.f;

    #pragma unroll 4
    for (int ks = 0; ks < KSTEPS; ks++) {
        int k0 = ks * 8 + tig;
        uint32_t a0[4], a1[4];
        a0[0] = tf32_bits(__ldg(A0 + k0));
        a0[1] = tf32_bits(__ldg(A1 + k0));
        a0[2] = tf32_bits(__ldg(A0 + k0 + 4));
        a0[3] = tf32_bits(__ldg(A1 + k0 + 4));
        a1[0] = tf32_bits(__ldg(A2 + k0));
        a1[1] = tf32_bits(__ldg(A3 + k0));
        a1[2] = tf32_bits(__ldg(A2 + k0 + 4));
        a1[3] = tf32_bits(__ldg(A3 + k0 + 4));
        #pragma unroll
        for (int nt = 0; nt < 7; nt++) {
            float2 b2 = __ldg(&Bf[((size_t)(ntg0 + nt) * KSTEPS + ks) * 32 + lane]);
            uint32_t b0 = __float_as_uint(b2.x);
            uint32_t b1 = __float_as_uint(b2.y);
            mma8(acc[0][nt], a0, b0, b1);
            mma8(acc[1][nt], a1, b0, b1);
        }
    }

    // epilogue: bases cols -> fp16 (half2 store), comb cols -> f32 + bias
    #pragma unroll
    for (int mt = 0; mt < 2; mt++) {
        int r1 = rowb + mt * 16 + gid;
        int r2 = r1 + 8;
        #pragma unroll
        for (int nt = 0; nt < 7; nt++) {
            int col = coln0 + nt * 8 + tig * 2;
            bool isB = (col < BF);
            float bx = 0.f, by = 0.f;
            if (!isB) { bx = bcomb[col - BF]; by = bcomb[col - BF + 1]; }
            if (r1 < M) {
                if (isB) {
                    __half2 hv = __floats2half2_rn(acc[mt][nt][0], acc[mt][nt][1]);
                    *reinterpret_cast<__half2*>(g_bases16 + (size_t)r1 * BF + col) = hv;
                } else {
                    float2 v = make_float2(acc[mt][nt][0] + bx, acc[mt][nt][1] + by);
                    *(float2*)(g_comb + (size_t)r1 * HBA + (col - BF)) = v;
                }
            }
            if (r2 < M) {
                if (isB) {
                    __half2 hv = __floats2half2_rn(acc[mt][nt][2], acc[mt][nt][3]);
                    *reinterpret_cast<__half2*>(g_bases16 + (size_t)r2 * BF + col) = hv;
                } else {
                    float2 v = make_float2(acc[mt][nt][2] + bx, acc[mt][nt][3] + by);
                    *(float2*)(g_comb + (size_t)r2 * HBA + (col - BF)) = v;
                }
            }
        }
    }
}

// ---------------- K7: warp-per-node aggregate + einsum + stats ----------------
#define AGG_WPB 8
__global__ __launch_bounds__(256) void k_agg(const float* __restrict__ conv_bias,
                                             const int* __restrict__ batchv, int n) {
    __shared__ float sAgg[AGG_WPB][3][128];
    __shared__ float sComb[AGG_WPB][96];
    __shared__ float sH [AGG_WPB][DD];   // per-warp h values for stats reduction
    __shared__ float sH2[AGG_WPB][DD];
    __shared__ int sg0;
    int t = threadIdx.x;
    int w = t >> 5, lane = t & 31;
    int node0 = blockIdx.x * AGG_WPB;
    int node = node0 + w;
    if (t == 0) sg0 = batchv[min(node0, n - 1)];
    __syncthreads();
    int g0 = sg0;

    if (node < n) {
        // prefetch comb early so it overlaps the edge loop
        sComb[w][lane]      = g_comb[(size_t)node * HBA + lane];
        sComb[w][lane + 32] = g_comb[(size_t)node * HBA + lane + 32];
        sComb[w][lane + 64] = g_comb[(size_t)node * HBA + lane + 64];

        const int2* ep = g_edge;
        float di = g_dinv[node];
        float4 bv = gather4(node, lane);
        float w2 = di * di;
        float4 asym = make_float4(bv.x * w2, bv.y * w2, bv.z * w2, bv.w * w2);
        float4 asum = bv;
        float4 amax = bv;
        int beg = g_off[node], end = g_off[node + 1];
        int j = beg;
        // unroll-by-4; fp16 bases payload halves gather traffic
        for (; j + 4 <= end; j += 4) {
            int2 e0 = __ldg(&ep[j]);
            int2 e1 = __ldg(&ep[j + 1]);
            int2 e2 = __ldg(&ep[j + 2]);
            int2 e3 = __ldg(&ep[j + 3]);
            float w0 = __int_as_float(e0.y);
            float w1 = __int_as_float(e1.y);
            float wS2 = __int_as_float(e2.y);
            float w3 = __int_as_float(e3.y);
            float4 m0 = gather4(e0.x, lane);
            float4 m1 = gather4(e1.x, lane);
            float4 m2 = gather4(e2.x, lane);
            float4 m3 = gather4(e3.x, lane);
            asym.x += m0.x * w0 + m1.x * w1 + m2.x * wS2 + m3.x * w3;
            asym.y += m0.y * w0 + m1.y * w1 + m2.y * wS2 + m3.y * w3;
            asym.z += m0.z * w0 + m1.z * w1 + m2.z * wS2 + m3.z * w3;
            asym.w += m0.w * w0 + m1.w * w1 + m2.w * wS2 + m3.w * w3;
            asum.x += m0.x + m1.x + m2.x + m3.x;
            asum.y += m0.y + m1.y + m2.y + m3.y;
            asum.z += m0.z + m1.z + m2.z + m3.z;
            asum.w += m0.w + m1.w + m2.w + m3.w;
            amax.x = fmaxf(fmaxf(fmaxf(amax.x, m0.x), fmaxf(m1.x, m2.x)), m3.x);
            amax.y = fmaxf(fmaxf(fmaxf(amax.y, m0.y), fmaxf(m1.y, m2.y)), m3.y);
            amax.z = fmaxf(fmaxf(fmaxf(amax.z, m0.z), fmaxf(m1.z, m2.z)), m3.z);
            amax.w = fmaxf(fmaxf(fmaxf(amax.w, m0.w), fmaxf(m1.w, m2.w)), m3.w);
        }
        for (; j < end; ++j) {
            int2 e0 = __ldg(&ep[j]);
            float ws = __int_as_float(e0.y);
            float4 m = gather4(e0.x, lane);
            asym.x += m.x * ws; asym.y += m.y * ws; asym.z += m.z * ws; asym.w += m.w * ws;
            asum.x += m.x;      asum.y += m.y;      asum.z += m.z;      asum.w += m.w;
            amax.x = fmaxf(amax.x, m.x); amax.y = fmaxf(amax.y, m.y);
            amax.z = fmaxf(amax.z, m.z); amax.w = fmaxf(amax.w, m.w);
        }
        ((float4*)sAgg[w][0])[lane] = asym;
        ((float4*)sAgg[w][1])[lane] = asum;
        ((float4*)sAgg[w][2])[lane] = amax;
        __syncwarp();
        int g = batchv[node];
        bool local = (g == g0);
        #pragma unroll
        for (int jh = 0; jh < 8; jh++) {  // jh = head
            int tt = jh * 32 + lane;      // output channel
            float acc = conv_bias[tt];
            #pragma unroll
            for (int k = 0; k < 12; k++)  // k = a*B + b
                acc += sComb[w][jh * 12 + k] * sAgg[w][k >> 2][(k & 3) * 32 + lane];
            g_h[(size_t)node * DD + tt] = acc;
            float a2 = acc * acc;
            if (local) {
                sH[w][tt] = acc;
                sH2[w][tt] = a2;
            } else {
                sH[w][tt] = 0.f;
                sH2[w][tt] = 0.f;
                atomicAdd(&g_S1[g * DD + tt], acc);
                atomicAdd(&g_S2[g * DD + tt], a2);
            }
        }
    } else {
        // inactive warp: zero its reduction rows
        #pragma unroll
        for (int jh = 0; jh < 8; jh++) {
            int tt = jh * 32 + lane;
            sH[w][tt] = 0.f;
            sH2[w][tt] = 0.f;
        }
    }
    __syncthreads();
    if (t < DD) {
        float s1 = 0.f, s2 = 0.f;
        #pragma unroll
        for (int ww = 0; ww < AGG_WPB; ww++) { s1 += sH[ww][t]; s2 += sH2[ww][t]; }
        atomicAdd(&g_S1[g0 * DD + t], s1);
        atomicAdd(&g_S2[g0 * DD + t], s2);
    }
}

// ---------------- K8: finalize GraphNorm statistics ----------------
__global__ void k_fin(const float* __restrict__ alpha_v) {
    int i = blockIdx.x * blockDim.x + threadIdx.x;
    if (i >= GG * DD) return;
    int g = i / DD, d = i % DD;
    int cs = g_gstart[g + 1] - g_gstart[g];
    float c = fmaxf((float)cs, 1.f);
    float m = g_S1[i] / c;
    float a = alpha_v[d];
    float var = g_S2[i] / c - (2.f * a - a * a) * m * m;
    g_mu[i] = a * m;
    g_istd[i] = rsqrtf(var + EPSV);
}

// ---------------- K9: normalize + relu ----------------
__global__ void k_out(float* __restrict__ out, const int* __restrict__ batchv,
                      const float* __restrict__ gamma, const float* __restrict__ beta, int n) {
    int idx = blockIdx.x * blockDim.x + threadIdx.x;
    int total = n * (DD / 4);
    if (idx >= total) return;
    int node = idx >> 6;          // DD/4 = 64 float4 per row
    int c4 = idx & 63;
    int g = __ldg(&batchv[node]);
    float4 hv = ((const float4*)g_h)[idx];
    int d = c4 * 4;
    float4 mu = *(const float4*)(g_mu + g * DD + d);
    float4 is = *(const float4*)(g_istd + g * DD + d);
    float4 ga = *(const float4*)(gamma + d);
    float4 be = *(const float4*)(beta + d);
    float4 r;
    r.x = fmaxf(0.f, ga.x * (hv.x - mu.x) * is.x + be.x);
    r.y = fmaxf(0.f, ga.y * (hv.y - mu.y) * is.y + be.y);
    r.z = fmaxf(0.f, ga.z * (hv.z - mu.z) * is.z + be.z);
    r.w = fmaxf(0.f, ga.w * (hv.w - mu.w) * is.w + be.w);
    ((float4*)out)[idx] = r;
}

// ---------------- launcher ----------------
extern "C" void kernel_launch(void* const* d_in, const int* in_sizes, int n_in,
                              void* d_out, int out_size) {
    const float* node      = (const float*)d_in[0];
    const float* Wb        = (const float*)d_in[2];
    const float* Wc        = (const float*)d_in[3];
    const float* bcomb     = (const float*)d_in[4];
    const float* conv_bias = (const float*)d_in[5];
    const float* gw        = (const float*)d_in[6];
    const float* gb        = (const float*)d_in[7];
    const float* gms       = (const float*)d_in[8];
    const int*   ei        = (const int*)d_in[9];
    const int*   batchv    = (const int*)d_in[10];
    int n = in_sizes[10];
    int e = in_sizes[9] / 2;
    const int* srcp = ei;
    const int* dstp = ei + e;
    float* out = (float*)d_out;

    int nb = (n + 1023) / 1024;   // 49 for n=50000; <= 64 (P2b) and <= 148 (residency)
    k_setup<<<nb, 1024>>>(n, e, nb, Wb, Wc, srcp, dstp, batchv);

    dim3 ggrid((n + TBM - 1) / TBM, 2);
    k_gemm_mma<<<ggrid, 256>>>(node, bcomb, n);

    k_agg<<<(n + AGG_WPB - 1) / AGG_WPB, 256>>>(conv_bias, batchv, n);
    k_fin<<<(GG * DD + 255) / 256, 256>>>(gms);
    k_out<<<(n * (DD / 4) + 255) / 256, 256>>>(out, batchv, gw, gb, n);
}